// round 15
// baseline (speedup 1.0000x reference)
#include <cuda_runtime.h>
#include <cuda_bf16.h>
#include <math.h>
#include <stdint.h>

#define Bq 256
#define Tq 10
#define BT 2560
#define Dq 512
#define Hq 1024
#define FFq 2048
#define NHq 16
#define HDq 64
#define Lq 2
#define G4 4096
#define G3 3072
#define HHq 512
#define LN_EPS 1e-5f

// ============================ PTX helpers ============================
__device__ __forceinline__ uint32_t smem_to_u32(const void* smem_ptr) {
    uint32_t addr;
    asm("{ .reg .u64 tmp; cvta.to.shared.u64 tmp, %1; cvt.u32.u64 %0, tmp; }"
        : "=r"(addr) : "l"(smem_ptr));
    return addr;
}
__device__ __forceinline__ void cp_async16(uint32_t smem, const void* gmem) {
    asm volatile("cp.async.cg.shared.global [%0], [%1], 16;" :: "r"(smem), "l"(gmem));
}
__device__ __forceinline__ void cp_commit() {
    asm volatile("cp.async.commit_group;" ::: "memory");
}
__device__ __forceinline__ void cp_wait1() {
    asm volatile("cp.async.wait_group 1;" ::: "memory");
}
__device__ __forceinline__ void cp_wait0() {
    asm volatile("cp.async.wait_group 0;" ::: "memory");
}
__device__ __forceinline__ void ldsm_x4(uint32_t (&r)[4], uint32_t addr) {
    asm volatile("ldmatrix.sync.aligned.m8n8.x4.shared.b16 {%0,%1,%2,%3}, [%4];"
        : "=r"(r[0]), "=r"(r[1]), "=r"(r[2]), "=r"(r[3]) : "r"(addr));
}
__device__ __forceinline__ void mma_bf16(float (&c)[4], const uint32_t (&a)[4],
                                         uint32_t b0, uint32_t b1) {
    asm volatile(
        "mma.sync.aligned.m16n8k16.row.col.f32.bf16.bf16.f32 "
        "{%0,%1,%2,%3}, {%4,%5,%6,%7}, {%8,%9}, {%0,%1,%2,%3};"
        : "+f"(c[0]), "+f"(c[1]), "+f"(c[2]), "+f"(c[3])
        : "r"(a[0]), "r"(a[1]), "r"(a[2]), "r"(a[3]), "r"(b0), "r"(b1));
}

__device__ __forceinline__ void bsplit(float v, __nv_bfloat16& h, __nv_bfloat16& l) {
    h = __float2bfloat16(v);
    l = __float2bfloat16(v - __bfloat162float(h));
}

// ============================ scratch buffers ============================
__device__ float g_h[BT * Hq];
__device__ float g_qkv[BT * G3];
__device__ float g_proj[BT * Hq];
__device__ float g_ln1[BT * Hq];
__device__ float g_gx[BT * G4];
__device__ float g_gh[Bq * G4];
__device__ float g_hst[Bq * Hq];
__device__ float g_cst[Bq * Hq];
__device__ float g_lo[BT * Hq];
__device__ float g_o1[BT * HHq];
__device__ float g_bsum[G4];
// bf16 split activations ([hi, lo, hi] along K)
__device__ __nv_bfloat16 g_xs[BT * 3 * Dq];
__device__ __nv_bfloat16 g_hs[BT * 3 * Hq];
__device__ __nv_bfloat16 g_attns[BT * 3 * Hq];
__device__ __nv_bfloat16 g_ln1s[BT * 3 * Hq];
__device__ __nv_bfloat16 g_ffs[BT * 3 * FFq];
__device__ __nv_bfloat16 g_hencs[BT * 3 * Hq];
__device__ __nv_bfloat16 g_hsts[Bq * 3 * Hq];
__device__ __nv_bfloat16 g_los[BT * 3 * Hq];
// bf16 split weights ([hi, hi, lo] along K)
__device__ __nv_bfloat16 g_fcws[Hq * 3 * Dq];
__device__ __nv_bfloat16 g_ipws[G3 * 3 * Hq];
__device__ __nv_bfloat16 g_opws[Hq * 3 * Hq];
__device__ __nv_bfloat16 g_ff1ws[FFq * 3 * Hq];
__device__ __nv_bfloat16 g_ff2ws[Hq * 3 * FFq];
__device__ __nv_bfloat16 g_wihs[G4 * 3 * Hq];
__device__ __nv_bfloat16 g_whhs[G4 * 3 * Hq];
__device__ __nv_bfloat16 g_o1ws[HHq * 3 * Hq];

// ============================ fused split of all matrices (1 launch) ============================
#define NSPLIT 9
struct SplitArgs {
    const float* in[NSPLIT];
    __nv_bfloat16* out[NSPLIT];
    int C[NSPLIT];
    int amode[NSPLIT];
    int cum[NSPLIT + 1];   // cumulative vec4 counts
};

__global__ void split_all(SplitArgs a) {
    int g = blockIdx.x * blockDim.x + threadIdx.x;
    if (g >= a.cum[NSPLIT]) return;
    int j = 0;
#pragma unroll
    for (int k = 1; k < NSPLIT; k++)
        if (g >= a.cum[k]) j = k;
    int i = (g - a.cum[j]) * 4;
    int C = a.C[j];
    int amode = a.amode[j];
    int r = i / C, c = i % C;
    float4 v = *reinterpret_cast<const float4*>(a.in[j] + i);
    __nv_bfloat16 h0, l0, h1, l1, h2, l2, h3, l3;
    bsplit(v.x, h0, l0); bsplit(v.y, h1, l1);
    bsplit(v.z, h2, l2); bsplit(v.w, h3, l3);
    __nv_bfloat162 hp0 = __halves2bfloat162(h0, h1);
    __nv_bfloat162 hp1 = __halves2bfloat162(h2, h3);
    __nv_bfloat162 lp0 = __halves2bfloat162(l0, l1);
    __nv_bfloat162 lp1 = __halves2bfloat162(l2, l3);
    uint2 hp = make_uint2(*reinterpret_cast<uint32_t*>(&hp0), *reinterpret_cast<uint32_t*>(&hp1));
    uint2 lp = make_uint2(*reinterpret_cast<uint32_t*>(&lp0), *reinterpret_cast<uint32_t*>(&lp1));
    __nv_bfloat16* out = a.out[j];
    size_t base = (size_t)r * 3 * C + c;
    *reinterpret_cast<uint2*>(out + base) = hp;
    *reinterpret_cast<uint2*>(out + base + C) = amode ? lp : hp;
    *reinterpret_cast<uint2*>(out + base + 2 * C) = amode ? hp : lp;
}

// ============================ mma.sync GEMM (3-stage, BK=64, 1 sync/iter — R10 proven) ============================
// BM=64 instantiations allow 2 CTAs/SM (acc regs fit under 128/thread); BM=128 stays 1.
template <int BM, bool RELU, bool WF32, bool WSPLIT>
__global__ __launch_bounds__(256, BM == 64 ? 2 : 1)
void mma_gemm(const __nv_bfloat16* __restrict__ A, const __nv_bfloat16* __restrict__ B,
              const float* __restrict__ bias, float* __restrict__ Cf,
              __nv_bfloat16* __restrict__ Cs, int M, int N, int K) {
    constexpr int BN = 128;
    constexpr int BK = 64;
    constexpr int STR = 72;          // smem row stride (bf16 elems) = 144B, conflict-free
    constexpr int MT = BM / 32;      // m16 tiles per warp
    constexpr int NT = 4;            // n8 tiles per warp (warp-N = 32)

    extern __shared__ __align__(16) __nv_bfloat16 dsmem[];
    __nv_bfloat16* sA = dsmem;                  // 3 * BM * STR
    __nv_bfloat16* sB = dsmem + 3 * BM * STR;   // 3 * BN * STR

    const int tid = threadIdx.x;
    const int wid = tid >> 5, lane = tid & 31;
    const int wm = wid >> 2, wn = wid & 3;
    const int m0 = blockIdx.y * BM, n0 = blockIdx.x * BN;

    const uint32_t sAu = smem_to_u32(sA);
    const uint32_t sBu = smem_to_u32(sB);

    float acc[MT][NT][4];
#pragma unroll
    for (int i = 0; i < MT; i++)
#pragma unroll
        for (int j = 0; j < NT; j++)
#pragma unroll
            for (int q = 0; q < 4; q++) acc[i][j][q] = 0.f;

    const int niter = K / BK;

    auto load_buf = [&](int buf, int k0) {
#pragma unroll
        for (int c = tid; c < BM * 8; c += 256) {
            int row = c >> 3, col = c & 7;
            uint32_t dst = sAu + (uint32_t)(buf * BM * STR + row * STR + col * 8) * 2u;
            cp_async16(dst, A + (size_t)(m0 + row) * K + k0 + col * 8);
        }
#pragma unroll
        for (int c = tid; c < BN * 8; c += 256) {
            int row = c >> 3, col = c & 7;
            uint32_t dst = sBu + (uint32_t)(buf * BN * STR + row * STR + col * 8) * 2u;
            cp_async16(dst, B + (size_t)(n0 + row) * K + k0 + col * 8);
        }
        cp_commit();
    };

    // prologue: two k-slices in flight
    load_buf(0, 0);
    load_buf(1, BK);

    for (int it = 0; it < niter; it++) {
        if (it + 1 < niter) cp_wait1(); else cp_wait0();
        __syncthreads();

        const int buf = it % 3;
        const uint32_t abase = sAu + (uint32_t)(buf * BM * STR) * 2u;
        const uint32_t bbase = sBu + (uint32_t)(buf * BN * STR) * 2u;

#pragma unroll
        for (int k16 = 0; k16 < 4; k16++) {
            uint32_t a[MT][4];
#pragma unroll
            for (int mt = 0; mt < MT; mt++) {
                int row = wm * (BM / 2) + mt * 16 + (lane & 15);
                int col = k16 * 16 + (lane >> 4) * 8;
                ldsm_x4(a[mt], abase + (uint32_t)(row * STR + col) * 2u);
            }
            uint32_t b[2][4];
#pragma unroll
            for (int p = 0; p < 2; p++) {
                int row = wn * 32 + p * 16 + ((lane >> 4) & 1) * 8 + (lane & 7);
                int col = k16 * 16 + ((lane >> 3) & 1) * 8;
                ldsm_x4(b[p], bbase + (uint32_t)(row * STR + col) * 2u);
            }
#pragma unroll
            for (int mt = 0; mt < MT; mt++)
#pragma unroll
                for (int nt = 0; nt < NT; nt++)
                    mma_bf16(acc[mt][nt], a[mt], b[nt >> 1][(nt & 1) * 2],
                             b[nt >> 1][(nt & 1) * 2 + 1]);
        }

        if (it + 2 < niter) load_buf((it + 2) % 3, (it + 2) * BK);
    }

    // epilogue
#pragma unroll
    for (int mt = 0; mt < MT; mt++) {
#pragma unroll
        for (int nt = 0; nt < NT; nt++) {
            int mb = m0 + wm * (BM / 2) + mt * 16 + (lane >> 2);
            int n = n0 + wn * 32 + nt * 8 + (lane & 3) * 2;
            float bb0 = 0.f, bb1 = 0.f;
            if (bias) { bb0 = __ldg(bias + n); bb1 = __ldg(bias + n + 1); }
#pragma unroll
            for (int hh = 0; hh < 2; hh++) {
                int m = mb + hh * 8;
                float v0 = acc[mt][nt][hh * 2] + bb0;
                float v1 = acc[mt][nt][hh * 2 + 1] + bb1;
                if (RELU) { v0 = fmaxf(v0, 0.f); v1 = fmaxf(v1, 0.f); }
                if (WF32) {
                    float2 v2 = make_float2(v0, v1);
                    *reinterpret_cast<float2*>(Cf + (size_t)m * N + n) = v2;
                }
                if (WSPLIT) {
                    __nv_bfloat16 h0, l0, h1, l1;
                    bsplit(v0, h0, l0);
                    bsplit(v1, h1, l1);
                    __nv_bfloat162 hp = __halves2bfloat162(h0, h1);
                    __nv_bfloat162 lp = __halves2bfloat162(l0, l1);
                    size_t sbse = (size_t)m * 3 * N + n;
                    *reinterpret_cast<uint32_t*>(Cs + sbse) = *reinterpret_cast<uint32_t*>(&hp);
                    *reinterpret_cast<uint32_t*>(Cs + sbse + N) = *reinterpret_cast<uint32_t*>(&lp);
                    *reinterpret_cast<uint32_t*>(Cs + sbse + 2 * N) = *reinterpret_cast<uint32_t*>(&hp);
                }
            }
        }
    }
}

// ============================ attention ============================
__global__ void attn_kernel(const float* __restrict__ qkv, __nv_bfloat16* __restrict__ outs) {
    __shared__ float qs[Tq][HDq], ks[Tq][HDq], vs[Tq][HDq];
    __shared__ float sc[Tq][Tq];
    const int bh = blockIdx.x;
    const int b = bh >> 4;
    const int hh = bh & 15;
    const int tid = threadIdx.x;

    const size_t base = (size_t)b * Tq * G3 + hh * HDq + tid;
#pragma unroll
    for (int t = 0; t < Tq; t++) {
        size_t rb = base + (size_t)t * G3;
        qs[t][tid] = qkv[rb];
        ks[t][tid] = qkv[rb + Hq];
        vs[t][tid] = qkv[rb + 2 * Hq];
    }
    __syncthreads();

    for (int idx = tid; idx < Tq * Tq; idx += 64) {
        int tqi = idx / Tq, tk = idx % Tq;
        float s = 0.f;
        if (tk <= tqi) {
#pragma unroll
            for (int d = 0; d < HDq; d++) s += qs[tqi][d] * ks[tk][d];
        }
        sc[tqi][tk] = s * 0.125f;
    }
    __syncthreads();

    if (tid < Tq) {
        int tqi = tid;
        float m = -1e30f;
        for (int k = 0; k <= tqi; k++) m = fmaxf(m, sc[tqi][k]);
        float sum = 0.f;
        for (int k = 0; k <= tqi; k++) {
            float e = expf(sc[tqi][k] - m);
            sc[tqi][k] = e;
            sum += e;
        }
        float inv = 1.f / sum;
        for (int k = 0; k <= tqi; k++) sc[tqi][k] *= inv;
    }
    __syncthreads();

    const size_t ob = (size_t)(b * Tq) * (3 * Hq) + hh * HDq + tid;
#pragma unroll
    for (int t = 0; t < Tq; t++) {
        float acc = 0.f;
        for (int k = 0; k <= t; k++) acc = fmaf(sc[t][k], vs[k][tid], acc);
        __nv_bfloat16 h, l;
        bsplit(acc, h, l);
        size_t r = ob + (size_t)t * (3 * Hq);
        outs[r] = h;
        outs[r + Hq] = l;
        outs[r + 2 * Hq] = h;
    }
}

// ============================ block reduce ============================
__device__ __forceinline__ void block_reduce2(float& a, float& b) {
#pragma unroll
    for (int o = 16; o > 0; o >>= 1) {
        a += __shfl_down_sync(0xFFFFFFFFu, a, o);
        b += __shfl_down_sync(0xFFFFFFFFu, b, o);
    }
    __shared__ float sa[8], sb[8];
    int w = threadIdx.x >> 5, lane = threadIdx.x & 31;
    int nw = blockDim.x >> 5;
    if (lane == 0) { sa[w] = a; sb[w] = b; }
    __syncthreads();
    if (w == 0) {
        a = (lane < nw) ? sa[lane] : 0.f;
        b = (lane < nw) ? sb[lane] : 0.f;
#pragma unroll
        for (int o = 4; o > 0; o >>= 1) {
            a += __shfl_down_sync(0xFFFFFFFFu, a, o);
            b += __shfl_down_sync(0xFFFFFFFFu, b, o);
        }
        if (lane == 0) { sa[0] = a; sb[0] = b; }
    }
    __syncthreads();
    a = sa[0];
    b = sb[0];
}

// ---------------- residual + LayerNorm + split ----------------
template <bool WF32>
__global__ void add_ln_kernel(const float* __restrict__ x, const float* __restrict__ r,
                              const float* __restrict__ w, const float* __restrict__ b,
                              float* __restrict__ outf, __nv_bfloat16* __restrict__ outs) {
    const int row = blockIdx.x;
    const float* xp = x + (size_t)row * Hq;
    const float* rp = r + (size_t)row * Hq;
    float v[4];
    float s = 0.f, s2 = 0.f;
#pragma unroll
    for (int i = 0; i < 4; i++) {
        int c = threadIdx.x + i * 256;
        v[i] = xp[c] + rp[c];
        s += v[i];
        s2 += v[i] * v[i];
    }
    block_reduce2(s, s2);
    float mean = s * (1.f / Hq);
    float var = s2 * (1.f / Hq) - mean * mean;
    float rstd = rsqrtf(var + LN_EPS);
#pragma unroll
    for (int i = 0; i < 4; i++) {
        int c = threadIdx.x + i * 256;
        float o = (v[i] - mean) * rstd * w[c] + b[c];
        if (WF32) outf[(size_t)row * Hq + c] = o;
        __nv_bfloat16 h, l;
        bsplit(o, h, l);
        size_t sbse = (size_t)row * 3 * Hq + c;
        outs[sbse] = h;
        outs[sbse + Hq] = l;
        outs[sbse + 2 * Hq] = h;
    }
}

// ---------------- LSTM ----------------
__global__ void bias_sum_kernel(const float* __restrict__ a, const float* __restrict__ b,
                                float* __restrict__ o) {
    int i = blockIdx.x * blockDim.x + threadIdx.x;
    if (i < G4) o[i] = a[i] + b[i];
}

__global__ void init_states_kernel(const float* __restrict__ uv, const float* __restrict__ gv,
                                   __nv_bfloat16* __restrict__ hsts, float* __restrict__ cst,
                                   int layer) {
    int idx = blockIdx.x * blockDim.x + threadIdx.x;
    int b = idx >> 10, u = idx & 1023;
    size_t src = ((size_t)b * Lq + layer) * Hq + u;
    float hv = uv[src];
    __nv_bfloat16 h, l;
    bsplit(hv, h, l);
    size_t hb = (size_t)b * 3 * Hq + u;
    hsts[hb] = h;
    hsts[hb + Hq] = l;
    hsts[hb + 2 * Hq] = h;
    cst[idx] = gv[src];
}

__device__ __forceinline__ float sigm(float x) { return 1.f / (1.f + expf(-x)); }

__global__ void lstm_cell_kernel(const float* __restrict__ gx, const float* __restrict__ gh,
                                 float* __restrict__ hst, float* __restrict__ cst,
                                 __nv_bfloat16* __restrict__ hsts,
                                 float* __restrict__ lo, __nv_bfloat16* __restrict__ los,
                                 int t) {
    int idx = blockIdx.x * blockDim.x + threadIdx.x;
    int b = idx >> 10, u = idx & 1023;
    const float* gxp = gx + (size_t)(b * Tq + t) * G4;
    const float* ghp = gh + (size_t)b * G4;
    float gi = gxp[u] + ghp[u];
    float gf = gxp[Hq + u] + ghp[Hq + u];
    float gg = gxp[2 * Hq + u] + ghp[2 * Hq + u];
    float go = gxp[3 * Hq + u] + ghp[3 * Hq + u];
    float c = sigm(gf) * cst[idx] + sigm(gi) * tanhf(gg);
    float hv = sigm(go) * tanhf(c);
    cst[idx] = c;
    hst[idx] = hv;
    __nv_bfloat16 h, l;
    bsplit(hv, h, l);
    size_t hb = (size_t)b * 3 * Hq + u;
    hsts[hb] = h;
    hsts[hb + Hq] = l;
    hsts[hb + 2 * Hq] = h;
    size_t lb = (size_t)(b * Tq + t);
    lo[lb * Hq + u] = hv;
    size_t ls = lb * 3 * Hq + u;
    los[ls] = h;
    los[ls + Hq] = l;
    los[ls + 2 * Hq] = h;
}

__global__ void store_states_kernel(const float* __restrict__ hst, const float* __restrict__ cst,
                                    float* __restrict__ out_uv, float* __restrict__ out_gv,
                                    int layer) {
    int idx = blockIdx.x * blockDim.x + threadIdx.x;
    int b = idx >> 10, u = idx & 1023;
    size_t dst = ((size_t)b * Lq + layer) * Hq + u;
    out_uv[dst] = hst[idx];
    out_gv[dst] = cst[idx];
}

// ---------------- head ----------------
__global__ void head_kernel(const float* __restrict__ o1, const float* __restrict__ w2,
                            const float* __restrict__ b2, float* __restrict__ out) {
    const int row = blockIdx.x;
    const float* xp = o1 + (size_t)row * HHq;
    float s0 = 0.f, s1 = 0.f;
    for (int i = threadIdx.x; i < HHq; i += blockDim.x) {
        float v = xp[i];
        s0 = fmaf(v, w2[i], s0);
        s1 = fmaf(v, w2[HHq + i], s1);
    }
    block_reduce2(s0, s1);
    if (threadIdx.x == 0) {
        float a = s0 + b2[0];
        float c = s1 + b2[1];
        float m = fmaxf(a, c);
        float lse = m + logf(expf(a - m) + expf(c - m));
        out[row * 2 + 0] = a - lse;
        out[row * 2 + 1] = c - lse;
    }
}

// ============================ host ============================
static float* symaddr(const void* sym) {
    void* p = nullptr;
    cudaGetSymbolAddress(&p, sym);
    return (float*)p;
}
static __nv_bfloat16* symaddr_bf(const void* sym) {
    void* p = nullptr;
    cudaGetSymbolAddress(&p, sym);
    return (__nv_bfloat16*)p;
}

#define SMEM_BM128 (3 * (128 + 128) * 72 * 2)
#define SMEM_BM64  (3 * (64 + 128) * 72 * 2)

extern "C" void kernel_launch(void* const* d_in, const int* in_sizes, int n_in,
                              void* d_out, int out_size) {
    const float* x          = (const float*)d_in[0];
    const float* user_vec   = (const float*)d_in[1];
    const float* game_vec   = (const float*)d_in[2];
    const float* fc_w       = (const float*)d_in[3];
    const float* fc_b       = (const float*)d_in[4];
    const float* in_proj_w  = (const float*)d_in[5];
    const float* in_proj_b  = (const float*)d_in[6];
    const float* out_proj_w = (const float*)d_in[7];
    const float* out_proj_b = (const float*)d_in[8];
    const float* ln1_w      = (const float*)d_in[9];
    const float* ln1_b      = (const float*)d_in[10];
    const float* ff1_w      = (const float*)d_in[11];
    const float* ff1_b      = (const float*)d_in[12];
    const float* ff2_w      = (const float*)d_in[13];
    const float* ff2_b      = (const float*)d_in[14];
    const float* ln2_w      = (const float*)d_in[15];
    const float* ln2_b      = (const float*)d_in[16];
    const float* w_ih       = (const float*)d_in[17];
    const float* w_hh       = (const float*)d_in[18];
    const float* b_ih       = (const float*)d_in[19];
    const float* b_hh       = (const float*)d_in[20];
    const float* out1_w     = (const float*)d_in[21];
    const float* out1_b     = (const float*)d_in[22];
    const float* out2_w     = (const float*)d_in[23];
    const float* out2_b     = (const float*)d_in[24];

    float* buf_h    = symaddr(g_h);
    float* buf_qkv  = symaddr(g_qkv);
    float* buf_proj = symaddr(g_proj);
    float* buf_ln1  = symaddr(g_ln1);
    float* buf_gx   = symaddr(g_gx);
    float* buf_gh   = symaddr(g_gh);
    float* buf_hst  = symaddr(g_hst);
    float* buf_cst  = symaddr(g_cst);
    float* buf_lo   = symaddr(g_lo);
    float* buf_o1   = symaddr(g_o1);
    float* buf_bsum = symaddr(g_bsum);

    __nv_bfloat16* s_x    = symaddr_bf(g_xs);
    __nv_bfloat16* s_h    = symaddr_bf(g_hs);
    __nv_bfloat16* s_attn = symaddr_bf(g_attns);
    __nv_bfloat16* s_ln1  = symaddr_bf(g_ln1s);
    __nv_bfloat16* s_ff   = symaddr_bf(g_ffs);
    __nv_bfloat16* s_henc = symaddr_bf(g_hencs);
    __nv_bfloat16* s_hst  = symaddr_bf(g_hsts);
    __nv_bfloat16* s_lo   = symaddr_bf(g_los);
    __nv_bfloat16* s_fcw  = symaddr_bf(g_fcws);
    __nv_bfloat16* s_ipw  = symaddr_bf(g_ipws);
    __nv_bfloat16* s_opw  = symaddr_bf(g_opws);
    __nv_bfloat16* s_ff1w = symaddr_bf(g_ff1ws);
    __nv_bfloat16* s_ff2w = symaddr_bf(g_ff2ws);
    __nv_bfloat16* s_wih  = symaddr_bf(g_wihs);
    __nv_bfloat16* s_whh  = symaddr_bf(g_whhs);
    __nv_bfloat16* s_o1w  = symaddr_bf(g_o1ws);

    float* out        = (float*)d_out;
    float* out_logits = out;
    float* out_gv     = out + (size_t)BT * 2;
    float* out_uv     = out_gv + (size_t)Bq * Lq * Hq;

    cudaFuncSetAttribute(mma_gemm<128, false, true, false>, cudaFuncAttributeMaxDynamicSharedMemorySize, SMEM_BM128);
    cudaFuncSetAttribute(mma_gemm<128, true, false, true>,  cudaFuncAttributeMaxDynamicSharedMemorySize, SMEM_BM128);
    cudaFuncSetAttribute(mma_gemm<64, true, true, true>,    cudaFuncAttributeMaxDynamicSharedMemorySize, SMEM_BM64);
    cudaFuncSetAttribute(mma_gemm<64, false, true, false>,  cudaFuncAttributeMaxDynamicSharedMemorySize, SMEM_BM64);
    cudaFuncSetAttribute(mma_gemm<64, true, true, false>,   cudaFuncAttributeMaxDynamicSharedMemorySize, SMEM_BM64);

    // ---- single fused split launch (9 matrices) ----
    {
        SplitArgs sa;
        const float* ins[NSPLIT]        = {fc_w, in_proj_w, out_proj_w, ff1_w, ff2_w, w_ih, w_hh, out1_w, x};
        __nv_bfloat16* outs_[NSPLIT]    = {s_fcw, s_ipw, s_opw, s_ff1w, s_ff2w, s_wih, s_whh, s_o1w, s_x};
        int Rs[NSPLIT]                  = {Hq, G3, Hq, FFq, Hq, G4, G4, HHq, BT};
        int Cs_[NSPLIT]                 = {Dq, Hq, Hq, Hq, FFq, Hq, Hq, Hq, Dq};
        int ams[NSPLIT]                 = {0, 0, 0, 0, 0, 0, 0, 0, 1};
        int cum = 0;
        for (int j = 0; j < NSPLIT; j++) {
            sa.in[j] = ins[j];
            sa.out[j] = outs_[j];
            sa.C[j] = Cs_[j];
            sa.amode[j] = ams[j];
            sa.cum[j] = cum;
            cum += Rs[j] * Cs_[j] / 4;
        }
        sa.cum[NSPLIT] = cum;
        split_all<<<(cum + 255) / 256, 256>>>(sa);
    }

    bias_sum_kernel<<<G4 / 256, 256>>>(b_ih, b_hh, buf_bsum);

    // fc: N=1024 -> BM=64 (320 blocks, 2/SM)
    mma_gemm<64, true, true, true><<<dim3(Hq / 128, BT / 64), 256, SMEM_BM64>>>(
        s_x, s_fcw, fc_b, buf_h, s_h, BT, Hq, 3 * Dq);

    for (int layer = 0; layer < Lq; layer++) {
        const __nv_bfloat16* hin_s = (layer == 0) ? s_h : s_lo;
        const float* hin_f = (layer == 0) ? buf_h : buf_lo;

        // qkv: N=3072, BM=128 (480 blocks)
        mma_gemm<128, false, true, false><<<dim3(G3 / 128, BT / 128), 256, SMEM_BM128>>>(
            hin_s, s_ipw, in_proj_b, buf_qkv, nullptr, BT, G3, 3 * Hq);

        attn_kernel<<<Bq * NHq, 64>>>(buf_qkv, s_attn);

        // out_proj: N=1024 -> BM=64 (320 blocks, 2/SM)
        mma_gemm<64, false, true, false><<<dim3(Hq / 128, BT / 64), 256, SMEM_BM64>>>(
            s_attn, s_opw, out_proj_b, buf_proj, nullptr, BT, Hq, 3 * Hq);

        add_ln_kernel<true><<<BT, 256>>>(hin_f, buf_proj, ln1_w, ln1_b, buf_ln1, s_ln1);

        // ff1: N=2048, BM=128 (320 blocks)
        mma_gemm<128, true, false, true><<<dim3(FFq / 128, BT / 128), 256, SMEM_BM128>>>(
            s_ln1, s_ff1w, ff1_b, nullptr, s_ff, BT, FFq, 3 * Hq);

        // ff2: N=1024 -> BM=64 (320 blocks, 2/SM)
        mma_gemm<64, false, true, false><<<dim3(Hq / 128, BT / 64), 256, SMEM_BM64>>>(
            s_ff, s_ff2w, ff2_b, buf_proj, nullptr, BT, Hq, 3 * FFq);

        add_ln_kernel<false><<<BT, 256>>>(buf_ln1, buf_proj, ln2_w, ln2_b, nullptr, s_henc);

        // gx: N=4096, BM=128 (640 blocks)
        mma_gemm<128, false, true, false><<<dim3(G4 / 128, BT / 128), 256, SMEM_BM128>>>(
            s_henc, s_wih, buf_bsum, buf_gx, nullptr, BT, G4, 3 * Hq);

        init_states_kernel<<<Bq * Hq / 256, 256>>>(user_vec, game_vec, s_hst, buf_cst, layer);

        for (int t = 0; t < Tq; t++) {
            mma_gemm<64, false, true, false><<<dim3(G4 / 128, Bq / 64), 256, SMEM_BM64>>>(
                s_hst, s_whh, nullptr, buf_gh, nullptr, Bq, G4, 3 * Hq);
            lstm_cell_kernel<<<Bq * Hq / 256, 256>>>(buf_gx, buf_gh, buf_hst, buf_cst,
                                                     s_hst, buf_lo, s_lo, t);
        }

        store_states_kernel<<<Bq * Hq / 256, 256>>>(buf_hst, buf_cst, out_uv, out_gv, layer);
    }

    // out1: N=512 -> BM=64 (160 blocks, 2/SM)
    mma_gemm<64, true, true, false><<<dim3(HHq / 128, BT / 64), 256, SMEM_BM64>>>(
        s_lo, s_o1w, out1_b, buf_o1, nullptr, BT, HHq, 3 * Hq);

    head_kernel<<<BT, 128>>>(buf_o1, out2_w, out2_b, out_logits);

    (void)in_sizes; (void)n_in; (void)out_size;
}

// round 16
// speedup vs baseline: 1.0780x; 1.0780x over previous
#include <cuda_runtime.h>
#include <cuda_bf16.h>
#include <math.h>
#include <stdint.h>

#define Bq 256
#define Tq 10
#define BT 2560
#define Dq 512
#define Hq 1024
#define FFq 2048
#define NHq 16
#define HDq 64
#define Lq 2
#define G4 4096
#define G3 3072
#define HHq 512
#define LN_EPS 1e-5f

// ============================ PTX helpers ============================
__device__ __forceinline__ uint32_t smem_to_u32(const void* smem_ptr) {
    uint32_t addr;
    asm("{ .reg .u64 tmp; cvta.to.shared.u64 tmp, %1; cvt.u32.u64 %0, tmp; }"
        : "=r"(addr) : "l"(smem_ptr));
    return addr;
}
__device__ __forceinline__ void cp_async16(uint32_t smem, const void* gmem) {
    asm volatile("cp.async.cg.shared.global [%0], [%1], 16;" :: "r"(smem), "l"(gmem));
}
__device__ __forceinline__ void cp_commit() {
    asm volatile("cp.async.commit_group;" ::: "memory");
}
__device__ __forceinline__ void cp_wait1() {
    asm volatile("cp.async.wait_group 1;" ::: "memory");
}
__device__ __forceinline__ void cp_wait0() {
    asm volatile("cp.async.wait_group 0;" ::: "memory");
}
__device__ __forceinline__ void ldsm_x4(uint32_t (&r)[4], uint32_t addr) {
    asm volatile("ldmatrix.sync.aligned.m8n8.x4.shared.b16 {%0,%1,%2,%3}, [%4];"
        : "=r"(r[0]), "=r"(r[1]), "=r"(r[2]), "=r"(r[3]) : "r"(addr));
}
__device__ __forceinline__ void mma_bf16(float (&c)[4], const uint32_t (&a)[4],
                                         uint32_t b0, uint32_t b1) {
    asm volatile(
        "mma.sync.aligned.m16n8k16.row.col.f32.bf16.bf16.f32 "
        "{%0,%1,%2,%3}, {%4,%5,%6,%7}, {%8,%9}, {%0,%1,%2,%3};"
        : "+f"(c[0]), "+f"(c[1]), "+f"(c[2]), "+f"(c[3])
        : "r"(a[0]), "r"(a[1]), "r"(a[2]), "r"(a[3]), "r"(b0), "r"(b1));
}

__device__ __forceinline__ void bsplit(float v, __nv_bfloat16& h, __nv_bfloat16& l) {
    h = __float2bfloat16(v);
    l = __float2bfloat16(v - __bfloat162float(h));
}

// ============================ scratch buffers ============================
__device__ float g_h[BT * Hq];
__device__ float g_qkv[BT * G3];
__device__ float g_proj[BT * Hq];
__device__ float g_ln1[BT * Hq];
__device__ float g_gx[BT * G4];
__device__ float g_gh[Bq * G4];
__device__ float g_hst[Bq * Hq];
__device__ float g_cst[Bq * Hq];
__device__ float g_lo[BT * Hq];
__device__ float g_o1[BT * HHq];
__device__ float g_bsum[G4];
// bf16 split activations ([hi, lo, hi] along K)
__device__ __nv_bfloat16 g_xs[BT * 3 * Dq];
__device__ __nv_bfloat16 g_hs[BT * 3 * Hq];
__device__ __nv_bfloat16 g_attns[BT * 3 * Hq];
__device__ __nv_bfloat16 g_ln1s[BT * 3 * Hq];
__device__ __nv_bfloat16 g_ffs[BT * 3 * FFq];
__device__ __nv_bfloat16 g_hencs[BT * 3 * Hq];
__device__ __nv_bfloat16 g_hsts[Bq * 3 * Hq];
__device__ __nv_bfloat16 g_los[BT * 3 * Hq];
// bf16 split weights ([hi, hi, lo] along K)
__device__ __nv_bfloat16 g_fcws[Hq * 3 * Dq];
__device__ __nv_bfloat16 g_ipws[G3 * 3 * Hq];
__device__ __nv_bfloat16 g_opws[Hq * 3 * Hq];
__device__ __nv_bfloat16 g_ff1ws[FFq * 3 * Hq];
__device__ __nv_bfloat16 g_ff2ws[Hq * 3 * FFq];
__device__ __nv_bfloat16 g_wihs[G4 * 3 * Hq];
__device__ __nv_bfloat16 g_whhs[G4 * 3 * Hq];
__device__ __nv_bfloat16 g_o1ws[HHq * 3 * Hq];

// ============================ fused split of all matrices (1 launch) ============================
#define NSPLIT 9
struct SplitArgs {
    const float* in[NSPLIT];
    __nv_bfloat16* out[NSPLIT];
    int C[NSPLIT];
    int amode[NSPLIT];
    int cum[NSPLIT + 1];   // cumulative vec4 counts
};

__global__ void split_all(SplitArgs a) {
    int g = blockIdx.x * blockDim.x + threadIdx.x;
    if (g >= a.cum[NSPLIT]) return;
    int j = 0;
#pragma unroll
    for (int k = 1; k < NSPLIT; k++)
        if (g >= a.cum[k]) j = k;
    int i = (g - a.cum[j]) * 4;
    int C = a.C[j];
    int amode = a.amode[j];
    int r = i / C, c = i % C;
    float4 v = *reinterpret_cast<const float4*>(a.in[j] + i);
    __nv_bfloat16 h0, l0, h1, l1, h2, l2, h3, l3;
    bsplit(v.x, h0, l0); bsplit(v.y, h1, l1);
    bsplit(v.z, h2, l2); bsplit(v.w, h3, l3);
    __nv_bfloat162 hp0 = __halves2bfloat162(h0, h1);
    __nv_bfloat162 hp1 = __halves2bfloat162(h2, h3);
    __nv_bfloat162 lp0 = __halves2bfloat162(l0, l1);
    __nv_bfloat162 lp1 = __halves2bfloat162(l2, l3);
    uint2 hp = make_uint2(*reinterpret_cast<uint32_t*>(&hp0), *reinterpret_cast<uint32_t*>(&hp1));
    uint2 lp = make_uint2(*reinterpret_cast<uint32_t*>(&lp0), *reinterpret_cast<uint32_t*>(&lp1));
    __nv_bfloat16* out = a.out[j];
    size_t base = (size_t)r * 3 * C + c;
    *reinterpret_cast<uint2*>(out + base) = hp;
    *reinterpret_cast<uint2*>(out + base + C) = amode ? lp : hp;
    *reinterpret_cast<uint2*>(out + base + 2 * C) = amode ? hp : lp;
}

// ============================ mma.sync GEMM (3-stage, BK=64, 1 sync/iter — R10 proven) ============================
// NO launch-bounds occupancy floor: register caps spill (R9, R15 evidence).
template <int BM, bool RELU, bool WF32, bool WSPLIT>
__global__ __launch_bounds__(256)
void mma_gemm(const __nv_bfloat16* __restrict__ A, const __nv_bfloat16* __restrict__ B,
              const float* __restrict__ bias, float* __restrict__ Cf,
              __nv_bfloat16* __restrict__ Cs, int M, int N, int K) {
    constexpr int BN = 128;
    constexpr int BK = 64;
    constexpr int STR = 72;          // smem row stride (bf16 elems) = 144B, conflict-free
    constexpr int MT = BM / 32;      // m16 tiles per warp
    constexpr int NT = 4;            // n8 tiles per warp (warp-N = 32)

    extern __shared__ __align__(16) __nv_bfloat16 dsmem[];
    __nv_bfloat16* sA = dsmem;                  // 3 * BM * STR
    __nv_bfloat16* sB = dsmem + 3 * BM * STR;   // 3 * BN * STR

    const int tid = threadIdx.x;
    const int wid = tid >> 5, lane = tid & 31;
    const int wm = wid >> 2, wn = wid & 3;
    const int m0 = blockIdx.y * BM, n0 = blockIdx.x * BN;

    const uint32_t sAu = smem_to_u32(sA);
    const uint32_t sBu = smem_to_u32(sB);

    float acc[MT][NT][4];
#pragma unroll
    for (int i = 0; i < MT; i++)
#pragma unroll
        for (int j = 0; j < NT; j++)
#pragma unroll
            for (int q = 0; q < 4; q++) acc[i][j][q] = 0.f;

    const int niter = K / BK;

    auto load_buf = [&](int buf, int k0) {
#pragma unroll
        for (int c = tid; c < BM * 8; c += 256) {
            int row = c >> 3, col = c & 7;
            uint32_t dst = sAu + (uint32_t)(buf * BM * STR + row * STR + col * 8) * 2u;
            cp_async16(dst, A + (size_t)(m0 + row) * K + k0 + col * 8);
        }
#pragma unroll
        for (int c = tid; c < BN * 8; c += 256) {
            int row = c >> 3, col = c & 7;
            uint32_t dst = sBu + (uint32_t)(buf * BN * STR + row * STR + col * 8) * 2u;
            cp_async16(dst, B + (size_t)(n0 + row) * K + k0 + col * 8);
        }
        cp_commit();
    };

    // prologue: two k-slices in flight
    load_buf(0, 0);
    load_buf(1, BK);

    for (int it = 0; it < niter; it++) {
        if (it + 1 < niter) cp_wait1(); else cp_wait0();
        __syncthreads();

        const int buf = it % 3;
        const uint32_t abase = sAu + (uint32_t)(buf * BM * STR) * 2u;
        const uint32_t bbase = sBu + (uint32_t)(buf * BN * STR) * 2u;

#pragma unroll
        for (int k16 = 0; k16 < 4; k16++) {
            uint32_t a[MT][4];
#pragma unroll
            for (int mt = 0; mt < MT; mt++) {
                int row = wm * (BM / 2) + mt * 16 + (lane & 15);
                int col = k16 * 16 + (lane >> 4) * 8;
                ldsm_x4(a[mt], abase + (uint32_t)(row * STR + col) * 2u);
            }
            uint32_t b[2][4];
#pragma unroll
            for (int p = 0; p < 2; p++) {
                int row = wn * 32 + p * 16 + ((lane >> 4) & 1) * 8 + (lane & 7);
                int col = k16 * 16 + ((lane >> 3) & 1) * 8;
                ldsm_x4(b[p], bbase + (uint32_t)(row * STR + col) * 2u);
            }
#pragma unroll
            for (int mt = 0; mt < MT; mt++)
#pragma unroll
                for (int nt = 0; nt < NT; nt++)
                    mma_bf16(acc[mt][nt], a[mt], b[nt >> 1][(nt & 1) * 2],
                             b[nt >> 1][(nt & 1) * 2 + 1]);
        }

        if (it + 2 < niter) load_buf((it + 2) % 3, (it + 2) * BK);
    }

    // epilogue
#pragma unroll
    for (int mt = 0; mt < MT; mt++) {
#pragma unroll
        for (int nt = 0; nt < NT; nt++) {
            int mb = m0 + wm * (BM / 2) + mt * 16 + (lane >> 2);
            int n = n0 + wn * 32 + nt * 8 + (lane & 3) * 2;
            float bb0 = 0.f, bb1 = 0.f;
            if (bias) { bb0 = __ldg(bias + n); bb1 = __ldg(bias + n + 1); }
#pragma unroll
            for (int hh = 0; hh < 2; hh++) {
                int m = mb + hh * 8;
                float v0 = acc[mt][nt][hh * 2] + bb0;
                float v1 = acc[mt][nt][hh * 2 + 1] + bb1;
                if (RELU) { v0 = fmaxf(v0, 0.f); v1 = fmaxf(v1, 0.f); }
                if (WF32) {
                    float2 v2 = make_float2(v0, v1);
                    *reinterpret_cast<float2*>(Cf + (size_t)m * N + n) = v2;
                }
                if (WSPLIT) {
                    __nv_bfloat16 h0, l0, h1, l1;
                    bsplit(v0, h0, l0);
                    bsplit(v1, h1, l1);
                    __nv_bfloat162 hp = __halves2bfloat162(h0, h1);
                    __nv_bfloat162 lp = __halves2bfloat162(l0, l1);
                    size_t sbse = (size_t)m * 3 * N + n;
                    *reinterpret_cast<uint32_t*>(Cs + sbse) = *reinterpret_cast<uint32_t*>(&hp);
                    *reinterpret_cast<uint32_t*>(Cs + sbse + N) = *reinterpret_cast<uint32_t*>(&lp);
                    *reinterpret_cast<uint32_t*>(Cs + sbse + 2 * N) = *reinterpret_cast<uint32_t*>(&hp);
                }
            }
        }
    }
}

// ============================ attention ============================
__global__ void attn_kernel(const float* __restrict__ qkv, __nv_bfloat16* __restrict__ outs) {
    __shared__ float qs[Tq][HDq], ks[Tq][HDq], vs[Tq][HDq];
    __shared__ float sc[Tq][Tq];
    const int bh = blockIdx.x;
    const int b = bh >> 4;
    const int hh = bh & 15;
    const int tid = threadIdx.x;

    const size_t base = (size_t)b * Tq * G3 + hh * HDq + tid;
#pragma unroll
    for (int t = 0; t < Tq; t++) {
        size_t rb = base + (size_t)t * G3;
        qs[t][tid] = qkv[rb];
        ks[t][tid] = qkv[rb + Hq];
        vs[t][tid] = qkv[rb + 2 * Hq];
    }
    __syncthreads();

    for (int idx = tid; idx < Tq * Tq; idx += 64) {
        int tqi = idx / Tq, tk = idx % Tq;
        float s = 0.f;
        if (tk <= tqi) {
#pragma unroll
            for (int d = 0; d < HDq; d++) s += qs[tqi][d] * ks[tk][d];
        }
        sc[tqi][tk] = s * 0.125f;
    }
    __syncthreads();

    if (tid < Tq) {
        int tqi = tid;
        float m = -1e30f;
        for (int k = 0; k <= tqi; k++) m = fmaxf(m, sc[tqi][k]);
        float sum = 0.f;
        for (int k = 0; k <= tqi; k++) {
            float e = expf(sc[tqi][k] - m);
            sc[tqi][k] = e;
            sum += e;
        }
        float inv = 1.f / sum;
        for (int k = 0; k <= tqi; k++) sc[tqi][k] *= inv;
    }
    __syncthreads();

    const size_t ob = (size_t)(b * Tq) * (3 * Hq) + hh * HDq + tid;
#pragma unroll
    for (int t = 0; t < Tq; t++) {
        float acc = 0.f;
        for (int k = 0; k <= t; k++) acc = fmaf(sc[t][k], vs[k][tid], acc);
        __nv_bfloat16 h, l;
        bsplit(acc, h, l);
        size_t r = ob + (size_t)t * (3 * Hq);
        outs[r] = h;
        outs[r + Hq] = l;
        outs[r + 2 * Hq] = h;
    }
}

// ============================ block reduce ============================
__device__ __forceinline__ void block_reduce2(float& a, float& b) {
#pragma unroll
    for (int o = 16; o > 0; o >>= 1) {
        a += __shfl_down_sync(0xFFFFFFFFu, a, o);
        b += __shfl_down_sync(0xFFFFFFFFu, b, o);
    }
    __shared__ float sa[8], sb[8];
    int w = threadIdx.x >> 5, lane = threadIdx.x & 31;
    int nw = blockDim.x >> 5;
    if (lane == 0) { sa[w] = a; sb[w] = b; }
    __syncthreads();
    if (w == 0) {
        a = (lane < nw) ? sa[lane] : 0.f;
        b = (lane < nw) ? sb[lane] : 0.f;
#pragma unroll
        for (int o = 4; o > 0; o >>= 1) {
            a += __shfl_down_sync(0xFFFFFFFFu, a, o);
            b += __shfl_down_sync(0xFFFFFFFFu, b, o);
        }
        if (lane == 0) { sa[0] = a; sb[0] = b; }
    }
    __syncthreads();
    a = sa[0];
    b = sb[0];
}

// ---------------- residual + LayerNorm + split ----------------
template <bool WF32>
__global__ void add_ln_kernel(const float* __restrict__ x, const float* __restrict__ r,
                              const float* __restrict__ w, const float* __restrict__ b,
                              float* __restrict__ outf, __nv_bfloat16* __restrict__ outs) {
    const int row = blockIdx.x;
    const float* xp = x + (size_t)row * Hq;
    const float* rp = r + (size_t)row * Hq;
    float v[4];
    float s = 0.f, s2 = 0.f;
#pragma unroll
    for (int i = 0; i < 4; i++) {
        int c = threadIdx.x + i * 256;
        v[i] = xp[c] + rp[c];
        s += v[i];
        s2 += v[i] * v[i];
    }
    block_reduce2(s, s2);
    float mean = s * (1.f / Hq);
    float var = s2 * (1.f / Hq) - mean * mean;
    float rstd = rsqrtf(var + LN_EPS);
#pragma unroll
    for (int i = 0; i < 4; i++) {
        int c = threadIdx.x + i * 256;
        float o = (v[i] - mean) * rstd * w[c] + b[c];
        if (WF32) outf[(size_t)row * Hq + c] = o;
        __nv_bfloat16 h, l;
        bsplit(o, h, l);
        size_t sbse = (size_t)row * 3 * Hq + c;
        outs[sbse] = h;
        outs[sbse + Hq] = l;
        outs[sbse + 2 * Hq] = h;
    }
}

// ---------------- LSTM ----------------
__global__ void bias_sum_kernel(const float* __restrict__ a, const float* __restrict__ b,
                                float* __restrict__ o) {
    int i = blockIdx.x * blockDim.x + threadIdx.x;
    if (i < G4) o[i] = a[i] + b[i];
}

__global__ void init_states_kernel(const float* __restrict__ uv, const float* __restrict__ gv,
                                   __nv_bfloat16* __restrict__ hsts, float* __restrict__ cst,
                                   int layer) {
    int idx = blockIdx.x * blockDim.x + threadIdx.x;
    int b = idx >> 10, u = idx & 1023;
    size_t src = ((size_t)b * Lq + layer) * Hq + u;
    float hv = uv[src];
    __nv_bfloat16 h, l;
    bsplit(hv, h, l);
    size_t hb = (size_t)b * 3 * Hq + u;
    hsts[hb] = h;
    hsts[hb + Hq] = l;
    hsts[hb + 2 * Hq] = h;
    cst[idx] = gv[src];
}

__device__ __forceinline__ float sigm(float x) { return 1.f / (1.f + expf(-x)); }

__global__ void lstm_cell_kernel(const float* __restrict__ gx, const float* __restrict__ gh,
                                 float* __restrict__ hst, float* __restrict__ cst,
                                 __nv_bfloat16* __restrict__ hsts,
                                 float* __restrict__ lo, __nv_bfloat16* __restrict__ los,
                                 int t) {
    int idx = blockIdx.x * blockDim.x + threadIdx.x;
    int b = idx >> 10, u = idx & 1023;
    const float* gxp = gx + (size_t)(b * Tq + t) * G4;
    const float* ghp = gh + (size_t)b * G4;
    float gi = gxp[u] + ghp[u];
    float gf = gxp[Hq + u] + ghp[Hq + u];
    float gg = gxp[2 * Hq + u] + ghp[2 * Hq + u];
    float go = gxp[3 * Hq + u] + ghp[3 * Hq + u];
    float c = sigm(gf) * cst[idx] + sigm(gi) * tanhf(gg);
    float hv = sigm(go) * tanhf(c);
    cst[idx] = c;
    hst[idx] = hv;
    __nv_bfloat16 h, l;
    bsplit(hv, h, l);
    size_t hb = (size_t)b * 3 * Hq + u;
    hsts[hb] = h;
    hsts[hb + Hq] = l;
    hsts[hb + 2 * Hq] = h;
    size_t lb = (size_t)(b * Tq + t);
    lo[lb * Hq + u] = hv;
    size_t ls = lb * 3 * Hq + u;
    los[ls] = h;
    los[ls + Hq] = l;
    los[ls + 2 * Hq] = h;
}

__global__ void store_states_kernel(const float* __restrict__ hst, const float* __restrict__ cst,
                                    float* __restrict__ out_uv, float* __restrict__ out_gv,
                                    int layer) {
    int idx = blockIdx.x * blockDim.x + threadIdx.x;
    int b = idx >> 10, u = idx & 1023;
    size_t dst = ((size_t)b * Lq + layer) * Hq + u;
    out_uv[dst] = hst[idx];
    out_gv[dst] = cst[idx];
}

// ---------------- head ----------------
__global__ void head_kernel(const float* __restrict__ o1, const float* __restrict__ w2,
                            const float* __restrict__ b2, float* __restrict__ out) {
    const int row = blockIdx.x;
    const float* xp = o1 + (size_t)row * HHq;
    float s0 = 0.f, s1 = 0.f;
    for (int i = threadIdx.x; i < HHq; i += blockDim.x) {
        float v = xp[i];
        s0 = fmaf(v, w2[i], s0);
        s1 = fmaf(v, w2[HHq + i], s1);
    }
    block_reduce2(s0, s1);
    if (threadIdx.x == 0) {
        float a = s0 + b2[0];
        float c = s1 + b2[1];
        float m = fmaxf(a, c);
        float lse = m + logf(expf(a - m) + expf(c - m));
        out[row * 2 + 0] = a - lse;
        out[row * 2 + 1] = c - lse;
    }
}

// ============================ host ============================
static float* symaddr(const void* sym) {
    void* p = nullptr;
    cudaGetSymbolAddress(&p, sym);
    return (float*)p;
}
static __nv_bfloat16* symaddr_bf(const void* sym) {
    void* p = nullptr;
    cudaGetSymbolAddress(&p, sym);
    return (__nv_bfloat16*)p;
}

#define SMEM_BM128 (3 * (128 + 128) * 72 * 2)
#define SMEM_BM64  (3 * (64 + 128) * 72 * 2)

extern "C" void kernel_launch(void* const* d_in, const int* in_sizes, int n_in,
                              void* d_out, int out_size) {
    const float* x          = (const float*)d_in[0];
    const float* user_vec   = (const float*)d_in[1];
    const float* game_vec   = (const float*)d_in[2];
    const float* fc_w       = (const float*)d_in[3];
    const float* fc_b       = (const float*)d_in[4];
    const float* in_proj_w  = (const float*)d_in[5];
    const float* in_proj_b  = (const float*)d_in[6];
    const float* out_proj_w = (const float*)d_in[7];
    const float* out_proj_b = (const float*)d_in[8];
    const float* ln1_w      = (const float*)d_in[9];
    const float* ln1_b      = (const float*)d_in[10];
    const float* ff1_w      = (const float*)d_in[11];
    const float* ff1_b      = (const float*)d_in[12];
    const float* ff2_w      = (const float*)d_in[13];
    const float* ff2_b      = (const float*)d_in[14];
    const float* ln2_w      = (const float*)d_in[15];
    const float* ln2_b      = (const float*)d_in[16];
    const float* w_ih       = (const float*)d_in[17];
    const float* w_hh       = (const float*)d_in[18];
    const float* b_ih       = (const float*)d_in[19];
    const float* b_hh       = (const float*)d_in[20];
    const float* out1_w     = (const float*)d_in[21];
    const float* out1_b     = (const float*)d_in[22];
    const float* out2_w     = (const float*)d_in[23];
    const float* out2_b     = (const float*)d_in[24];

    float* buf_h    = symaddr(g_h);
    float* buf_qkv  = symaddr(g_qkv);
    float* buf_proj = symaddr(g_proj);
    float* buf_ln1  = symaddr(g_ln1);
    float* buf_gx   = symaddr(g_gx);
    float* buf_gh   = symaddr(g_gh);
    float* buf_hst  = symaddr(g_hst);
    float* buf_cst  = symaddr(g_cst);
    float* buf_lo   = symaddr(g_lo);
    float* buf_o1   = symaddr(g_o1);
    float* buf_bsum = symaddr(g_bsum);

    __nv_bfloat16* s_x    = symaddr_bf(g_xs);
    __nv_bfloat16* s_h    = symaddr_bf(g_hs);
    __nv_bfloat16* s_attn = symaddr_bf(g_attns);
    __nv_bfloat16* s_ln1  = symaddr_bf(g_ln1s);
    __nv_bfloat16* s_ff   = symaddr_bf(g_ffs);
    __nv_bfloat16* s_henc = symaddr_bf(g_hencs);
    __nv_bfloat16* s_hst  = symaddr_bf(g_hsts);
    __nv_bfloat16* s_lo   = symaddr_bf(g_los);
    __nv_bfloat16* s_fcw  = symaddr_bf(g_fcws);
    __nv_bfloat16* s_ipw  = symaddr_bf(g_ipws);
    __nv_bfloat16* s_opw  = symaddr_bf(g_opws);
    __nv_bfloat16* s_ff1w = symaddr_bf(g_ff1ws);
    __nv_bfloat16* s_ff2w = symaddr_bf(g_ff2ws);
    __nv_bfloat16* s_wih  = symaddr_bf(g_wihs);
    __nv_bfloat16* s_whh  = symaddr_bf(g_whhs);
    __nv_bfloat16* s_o1w  = symaddr_bf(g_o1ws);

    float* out        = (float*)d_out;
    float* out_logits = out;
    float* out_gv     = out + (size_t)BT * 2;
    float* out_uv     = out_gv + (size_t)Bq * Lq * Hq;

    cudaFuncSetAttribute(mma_gemm<128, false, true, false>, cudaFuncAttributeMaxDynamicSharedMemorySize, SMEM_BM128);
    cudaFuncSetAttribute(mma_gemm<128, true, false, true>,  cudaFuncAttributeMaxDynamicSharedMemorySize, SMEM_BM128);
    cudaFuncSetAttribute(mma_gemm<64, true, true, true>,    cudaFuncAttributeMaxDynamicSharedMemorySize, SMEM_BM64);
    cudaFuncSetAttribute(mma_gemm<64, false, true, false>,  cudaFuncAttributeMaxDynamicSharedMemorySize, SMEM_BM64);
    cudaFuncSetAttribute(mma_gemm<64, true, true, false>,   cudaFuncAttributeMaxDynamicSharedMemorySize, SMEM_BM64);

    // ---- single fused split launch (9 matrices) ----
    {
        SplitArgs sa;
        const float* ins[NSPLIT]        = {fc_w, in_proj_w, out_proj_w, ff1_w, ff2_w, w_ih, w_hh, out1_w, x};
        __nv_bfloat16* outs_[NSPLIT]    = {s_fcw, s_ipw, s_opw, s_ff1w, s_ff2w, s_wih, s_whh, s_o1w, s_x};
        int Rs[NSPLIT]                  = {Hq, G3, Hq, FFq, Hq, G4, G4, HHq, BT};
        int Cs_[NSPLIT]                 = {Dq, Hq, Hq, Hq, FFq, Hq, Hq, Hq, Dq};
        int ams[NSPLIT]                 = {0, 0, 0, 0, 0, 0, 0, 0, 1};
        int cum = 0;
        for (int j = 0; j < NSPLIT; j++) {
            sa.in[j] = ins[j];
            sa.out[j] = outs_[j];
            sa.C[j] = Cs_[j];
            sa.amode[j] = ams[j];
            sa.cum[j] = cum;
            cum += Rs[j] * Cs_[j] / 4;
        }
        sa.cum[NSPLIT] = cum;
        split_all<<<(cum + 255) / 256, 256>>>(sa);
    }

    bias_sum_kernel<<<G4 / 256, 256>>>(b_ih, b_hh, buf_bsum);

    // fc: N=1024 -> BM=64 (320 blocks)
    mma_gemm<64, true, true, true><<<dim3(Hq / 128, BT / 64), 256, SMEM_BM64>>>(
        s_x, s_fcw, fc_b, buf_h, s_h, BT, Hq, 3 * Dq);

    for (int layer = 0; layer < Lq; layer++) {
        const __nv_bfloat16* hin_s = (layer == 0) ? s_h : s_lo;
        const float* hin_f = (layer == 0) ? buf_h : buf_lo;

        // qkv: N=3072, BM=128 (480 blocks)
        mma_gemm<128, false, true, false><<<dim3(G3 / 128, BT / 128), 256, SMEM_BM128>>>(
            hin_s, s_ipw, in_proj_b, buf_qkv, nullptr, BT, G3, 3 * Hq);

        attn_kernel<<<Bq * NHq, 64>>>(buf_qkv, s_attn);

        // out_proj: N=1024 -> BM=64 (320 blocks)
        mma_gemm<64, false, true, false><<<dim3(Hq / 128, BT / 64), 256, SMEM_BM64>>>(
            s_attn, s_opw, out_proj_b, buf_proj, nullptr, BT, Hq, 3 * Hq);

        add_ln_kernel<true><<<BT, 256>>>(hin_f, buf_proj, ln1_w, ln1_b, buf_ln1, s_ln1);

        // ff1: N=2048, BM=128 (320 blocks)
        mma_gemm<128, true, false, true><<<dim3(FFq / 128, BT / 128), 256, SMEM_BM128>>>(
            s_ln1, s_ff1w, ff1_b, nullptr, s_ff, BT, FFq, 3 * Hq);

        // ff2: N=1024 -> BM=64 (320 blocks)
        mma_gemm<64, false, true, false><<<dim3(Hq / 128, BT / 64), 256, SMEM_BM64>>>(
            s_ff, s_ff2w, ff2_b, buf_proj, nullptr, BT, Hq, 3 * FFq);

        add_ln_kernel<false><<<BT, 256>>>(buf_ln1, buf_proj, ln2_w, ln2_b, nullptr, s_henc);

        // gx: N=4096, BM=128 (640 blocks)
        mma_gemm<128, false, true, false><<<dim3(G4 / 128, BT / 128), 256, SMEM_BM128>>>(
            s_henc, s_wih, buf_bsum, buf_gx, nullptr, BT, G4, 3 * Hq);

        init_states_kernel<<<Bq * Hq / 256, 256>>>(user_vec, game_vec, s_hst, buf_cst, layer);

        for (int t = 0; t < Tq; t++) {
            mma_gemm<64, false, true, false><<<dim3(G4 / 128, Bq / 64), 256, SMEM_BM64>>>(
                s_hst, s_whh, nullptr, buf_gh, nullptr, Bq, G4, 3 * Hq);
            lstm_cell_kernel<<<Bq * Hq / 256, 256>>>(buf_gx, buf_gh, buf_hst, buf_cst,
                                                     s_hst, buf_lo, s_lo, t);
        }

        store_states_kernel<<<Bq * Hq / 256, 256>>>(buf_hst, buf_cst, out_uv, out_gv, layer);
    }

    // out1: N=512 -> BM=64 (160 blocks)
    mma_gemm<64, true, true, false><<<dim3(HHq / 128, BT / 64), 256, SMEM_BM64>>>(
        s_lo, s_o1w, out1_b, buf_o1, nullptr, BT, HHq, 3 * Hq);

    head_kernel<<<BT, 128>>>(buf_o1, out2_w, out2_b, out_logits);

    (void)in_sizes; (void)n_in; (void)out_size;
}